// round 2
// baseline (speedup 1.0000x reference)
#include <cuda_runtime.h>
#include <math.h>

#define NQ 131072
#define NS 262144
#define D  256
#define C  64

// ---- device scratch (no allocations allowed) ----
__device__ float g_psum[C * D];
__device__ int   g_cnt[C];
__device__ float g_Pt[D * C];   // [k][c], pre-divided by p_norm

extern __shared__ float smem[];

// ---------------- zero accumulators ----------------
__global__ void k_zero() {
    int i = blockIdx.x * blockDim.x + threadIdx.x;
    if (i < C * D) g_psum[i] = 0.0f;
    if (i < C)     g_cnt[i]  = 0;
}

// ---------------- segment sum ----------------
// 256 threads: 4 rows in flight (64 lanes/row, float4 per lane).
// NOTE: labels arrive as int32 (harness converts int64 -> int32).
__global__ void __launch_bounds__(256) k_seg(const float* __restrict__ S,
                                             const int* __restrict__ L) {
    float* acc = smem;                    // 64*256 floats
    int*   cnt = (int*)(smem + C * D);    // 64 ints

    for (int i = threadIdx.x; i < C * D; i += 256) acc[i] = 0.0f;
    if (threadIdx.x < C) cnt[threadIdx.x] = 0;
    __syncthreads();

    const int g = threadIdx.x >> 6;       // row group 0..3
    const int lane = threadIdx.x & 63;    // dim group (float4)
    const int stride = gridDim.x * 4;

    for (int row = blockIdx.x * 4 + g; row < NS; row += stride) {
        int lab = __ldg(&L[row]);
        float4 v = __ldg(((const float4*)S) + row * (D / 4) + lane);
        if ((unsigned)lab < (unsigned)C) {
            float* a = acc + lab * D + lane * 4;
            atomicAdd(a + 0, v.x);
            atomicAdd(a + 1, v.y);
            atomicAdd(a + 2, v.z);
            atomicAdd(a + 3, v.w);
            if (lane == 0) atomicAdd(&cnt[lab], 1);
        }
    }
    __syncthreads();

    for (int i = threadIdx.x; i < C * D; i += 256) atomicAdd(&g_psum[i], acc[i]);
    if (threadIdx.x < C) atomicAdd(&g_cnt[threadIdx.x], cnt[threadIdx.x]);
}

// ---------------- finalize prototypes ----------------
// one block per class, 64 threads (4 dims each)
__global__ void k_fin() {
    __shared__ float red[64];
    int c = blockIdx.x, t = threadIdx.x;
    float denom = fmaxf((float)g_cnt[c], 1.0f);
    float4 p = *(float4*)&g_psum[c * D + t * 4];
    float inv_d = 1.0f / denom;
    p.x *= inv_d; p.y *= inv_d; p.z *= inv_d; p.w *= inv_d;
    red[t] = p.x * p.x + p.y * p.y + p.z * p.z + p.w * p.w;
    __syncthreads();
    for (int s = 32; s > 0; s >>= 1) {
        if (t < s) red[t] += red[t + s];
        __syncthreads();
    }
    float pn = fmaxf(sqrtf(red[0]), 1e-8f);
    float inv = 1.0f / pn;
    g_Pt[(t * 4 + 0) * C + c] = p.x * inv;
    g_Pt[(t * 4 + 1) * C + c] = p.y * inv;
    g_Pt[(t * 4 + 2) * C + c] = p.z * inv;
    g_Pt[(t * 4 + 3) * C + c] = p.w * inv;
}

// fast exp on the FMA pipe (no MUFU): exp(x) = 2^(x*log2e), magic-number
// range reduction, deg-5 poly for 2^f on [-0.5, 0.5].
__device__ __forceinline__ float fexp(float x) {
    float y = x * 1.442695041f;
    float r = y + 12582912.0f;                       // round-to-nearest
    int n = __float_as_int(r) - 0x4B400000;
    float f = y - (r - 12582912.0f);                 // f in [-0.5, 0.5]
    float p = 1.3333558e-3f;
    p = fmaf(p, f, 9.6181291e-3f);
    p = fmaf(p, f, 5.5504109e-2f);
    p = fmaf(p, f, 2.4022651e-1f);
    p = fmaf(p, f, 6.9314718e-1f);
    p = fmaf(p, f, 1.0f);
    return __int_as_float(__float_as_int(p) + (n << 23));
}

// ---------------- query kernel ----------------
// 512 blocks x 256 threads; 256 queries/block; K in 4 chunks of 64.
// thread tile: 8 queries x 8 classes. smem: Qs[256][68] + Ps[64][64] + qns[256]
#define QPAD 68
__global__ void __launch_bounds__(256, 2) k_query(const float* __restrict__ Q,
                                                  float* __restrict__ out) {
    float* Qs  = smem;                  // 256*68
    float* Ps  = smem + 256 * QPAD;     // 64*64
    float* qns = Ps + 64 * 64;          // 256

    const int tid = threadIdx.x;
    const int qbase = blockIdx.x * 256;
    const int qt = tid >> 3;            // 0..31
    const int ct = tid & 7;             // 0..7

    float acc[8][8];
#pragma unroll
    for (int i = 0; i < 8; i++)
#pragma unroll
        for (int j = 0; j < 8; j++) acc[i][j] = 0.0f;

    float ssq = 0.0f;

    for (int chunk = 0; chunk < 4; chunk++) {
        __syncthreads();
        // stage Q chunk: thread tid owns query row (qbase+tid), 64 floats
        const float4* src = (const float4*)(Q + (size_t)(qbase + tid) * D + chunk * 64);
#pragma unroll
        for (int i = 0; i < 16; i++) {
            float4 v = __ldg(src + i);
            ssq += v.x * v.x + v.y * v.y + v.z * v.z + v.w * v.w;
            *(float4*)&Qs[tid * QPAD + i * 4] = v;
        }
        // stage P chunk: 64k x 64c = 1024 float4
        const float4* ps = (const float4*)(g_Pt + chunk * 64 * C);
#pragma unroll
        for (int i = 0; i < 4; i++)
            ((float4*)Ps)[tid + i * 256] = ps[tid + i * 256];
        __syncthreads();

#pragma unroll 4
        for (int kk = 0; kk < 64; kk++) {
            float4 pa = *(float4*)&Ps[kk * 64 + ct * 8];
            float4 pb = *(float4*)&Ps[kk * 64 + ct * 8 + 4];
            float qv[8];
#pragma unroll
            for (int i = 0; i < 8; i++) qv[i] = Qs[(qt + 32 * i) * QPAD + kk];
#pragma unroll
            for (int i = 0; i < 8; i++) {
                acc[i][0] = fmaf(qv[i], pa.x, acc[i][0]);
                acc[i][1] = fmaf(qv[i], pa.y, acc[i][1]);
                acc[i][2] = fmaf(qv[i], pa.z, acc[i][2]);
                acc[i][3] = fmaf(qv[i], pa.w, acc[i][3]);
                acc[i][4] = fmaf(qv[i], pb.x, acc[i][4]);
                acc[i][5] = fmaf(qv[i], pb.y, acc[i][5]);
                acc[i][6] = fmaf(qv[i], pb.z, acc[i][6]);
                acc[i][7] = fmaf(qv[i], pb.w, acc[i][7]);
            }
        }
    }

    qns[tid] = ssq;       // sumsq for query (qbase+tid)
    __syncthreads();

    // epilogue: per query, scale by 1/q_norm, log_softmax over 64 classes
    // (8 local classes + butterfly over the 8-lane ct group)
#pragma unroll
    for (int i = 0; i < 8; i++) {
        int q = qt + 32 * i;
        float qn = fmaxf(sqrtf(qns[q]), 1e-8f);
        float invqn = 1.0f / qn;
        float s[8];
        float m = -3.4e38f;
#pragma unroll
        for (int j = 0; j < 8; j++) {
            s[j] = acc[i][j] * invqn;
            m = fmaxf(m, s[j]);
        }
#pragma unroll
        for (int w = 1; w < 8; w <<= 1)
            m = fmaxf(m, __shfl_xor_sync(0xffffffffu, m, w));
        float sum = 0.0f;
#pragma unroll
        for (int j = 0; j < 8; j++) sum += fexp(s[j] - m);
#pragma unroll
        for (int w = 1; w < 8; w <<= 1)
            sum += __shfl_xor_sync(0xffffffffu, sum, w);
        float lse = m + logf(sum);
        float4 o0, o1;
        o0.x = s[0] - lse; o0.y = s[1] - lse; o0.z = s[2] - lse; o0.w = s[3] - lse;
        o1.x = s[4] - lse; o1.y = s[5] - lse; o1.z = s[6] - lse; o1.w = s[7] - lse;
        float4* dst = (float4*)(out + (size_t)(qbase + q) * C + ct * 8);
        dst[0] = o0;
        dst[1] = o1;
    }
}

extern "C" void kernel_launch(void* const* d_in, const int* in_sizes, int n_in,
                              void* d_out, int out_size) {
    const float* support = (const float*)d_in[0];
    const int*   labels  = (const int*)d_in[1];
    const float* query   = (const float*)d_in[2];
    float*       out     = (float*)d_out;

    const int seg_smem = (C * D) * 4 + C * 4;                       // 65792
    const int qry_smem = (256 * QPAD + 64 * 64 + 256) * 4;          // 87040
    cudaFuncSetAttribute(k_seg,   cudaFuncAttributeMaxDynamicSharedMemorySize, seg_smem);
    cudaFuncSetAttribute(k_query, cudaFuncAttributeMaxDynamicSharedMemorySize, qry_smem);

    k_zero<<<(C * D + 255) / 256, 256>>>();
    k_seg<<<296, 256, seg_smem>>>(support, labels);
    k_fin<<<C, 64>>>();
    k_query<<<NQ / 256, 256, qry_smem>>>(query, out);
}

// round 4
// speedup vs baseline: 2.2966x; 2.2966x over previous
#include <cuda_runtime.h>
#include <cuda_bf16.h>
#include <math.h>
#include <stdint.h>

#define NQ 131072
#define NS 262144
#define D  256
#define C  64
#define MT 128                 // query tile rows per CTA

// ---------------- device scratch ----------------
__device__ float g_psum[C * D];
__device__ int   g_cnt[C];
__device__ uint4 g_Pbf4[2048];   // 32KB: prototypes bf16 [64][256], XOR-swizzled, /p_norm

extern __shared__ char smem_raw[];

__device__ __forceinline__ uint32_t smem_u32(const void* p) {
    uint32_t a;
    asm("{ .reg .u64 t; cvta.to.shared.u64 t, %1; cvt.u32.u64 %0, t; }" : "=r"(a) : "l"(p));
    return a;
}

// swizzle: rows are 512B (256 bf16); 16B granule g at row r lives at (g ^ (r&7))
// (XOR only touches low 3 bits of g, so granules stay within their 128B half-line)

// ---------------- zero ----------------
__global__ void k_zero() {
    int i = blockIdx.x * blockDim.x + threadIdx.x;
    if (i < C * D) g_psum[i] = 0.0f;
    if (i < C)     g_cnt[i]  = 0;
}

// ---------------- segment sum: ownership-partitioned, NO shared atomics ----------------
// 256 blocks x 256 thr; block owns 1024 rows; thread t exclusively owns dim t.
#define RPB 1024
__global__ void __launch_bounds__(256, 2) k_seg(const float* __restrict__ S,
                                                const int* __restrict__ L) {
    float* acc = (float*)smem_raw;            // [64][256]
    int*   cnt = (int*)(smem_raw + C * D * 4);

    for (int i = threadIdx.x; i < C * D; i += 256) acc[i] = 0.0f;
    if (threadIdx.x < C) cnt[threadIdx.x] = 0;
    __syncthreads();

    const int dim  = threadIdx.x;
    const int base = blockIdx.x * RPB;
    const float* Sp = S + dim;

    for (int it = 0; it < RPB; it += 16) {
        int r = base + it;
        int4 la = __ldg((const int4*)(L + r));
        int4 lb = __ldg((const int4*)(L + r + 4));
        int4 lc = __ldg((const int4*)(L + r + 8));
        int4 ld = __ldg((const int4*)(L + r + 12));
        int lab[16] = { la.x, la.y, la.z, la.w, lb.x, lb.y, lb.z, lb.w,
                        lc.x, lc.y, lc.z, lc.w, ld.x, ld.y, ld.z, ld.w };
        float v[16];
#pragma unroll
        for (int j = 0; j < 16; j++) v[j] = __ldg(Sp + (size_t)(r + j) * D);
#pragma unroll
        for (int j = 0; j < 16; j++) acc[lab[j] * D + dim] += v[j];
        if (threadIdx.x == 0) {
#pragma unroll
            for (int j = 0; j < 16; j++) atomicAdd(&cnt[lab[j]], 1);
        }
    }
    __syncthreads();

    for (int i = threadIdx.x; i < C * D; i += 256) atomicAdd(&g_psum[i], acc[i]);
    if (threadIdx.x < C) atomicAdd(&g_cnt[threadIdx.x], cnt[threadIdx.x]);
}

// ---------------- finalize: normalized bf16 prototypes, pre-swizzled ----------------
__global__ void k_fin() {
    __shared__ float red[64];
    int c = blockIdx.x, t = threadIdx.x;
    float denom = fmaxf((float)g_cnt[c], 1.0f);
    float4 p = *(float4*)&g_psum[c * D + t * 4];
    float inv_d = 1.0f / denom;
    p.x *= inv_d; p.y *= inv_d; p.z *= inv_d; p.w *= inv_d;
    red[t] = p.x * p.x + p.y * p.y + p.z * p.z + p.w * p.w;
    __syncthreads();
    for (int s = 32; s > 0; s >>= 1) {
        if (t < s) red[t] += red[t + s];
        __syncthreads();
    }
    float inv = 1.0f / fmaxf(sqrtf(red[0]), 1e-8f);
    float pv[4] = { p.x * inv, p.y * inv, p.z * inv, p.w * inv };
    __nv_bfloat16* dst = (__nv_bfloat16*)g_Pbf4;
#pragma unroll
    for (int j = 0; j < 4; j++) {
        int k = t * 4 + j;
        uint32_t byte = (uint32_t)(c * 512 + ((((k >> 3) ^ (c & 7))) << 4) + (k & 7) * 2);
        dst[byte >> 1] = __float2bfloat16_rn(pv[j]);
    }
}

// fast exp on the FMA pipe
__device__ __forceinline__ float fexp(float x) {
    float y = x * 1.442695041f;
    float r = y + 12582912.0f;
    int n = __float_as_int(r) - 0x4B400000;
    float f = y - (r - 12582912.0f);
    float p = 1.3333558e-3f;
    p = fmaf(p, f, 9.6181291e-3f);
    p = fmaf(p, f, 5.5504109e-2f);
    p = fmaf(p, f, 2.4022651e-1f);
    p = fmaf(p, f, 6.9314718e-1f);
    p = fmaf(p, f, 1.0f);
    return __int_as_float(__float_as_int(p) + (n << 23));
}

__device__ __forceinline__ void ldm4(uint32_t& r0, uint32_t& r1, uint32_t& r2, uint32_t& r3,
                                     uint32_t addr) {
    asm volatile("ldmatrix.sync.aligned.m8n8.x4.shared.b16 {%0,%1,%2,%3}, [%4];"
                 : "=r"(r0), "=r"(r1), "=r"(r2), "=r"(r3) : "r"(addr));
}
__device__ __forceinline__ void mma16816(float* d, uint32_t a0, uint32_t a1, uint32_t a2,
                                         uint32_t a3, uint32_t b0, uint32_t b1) {
    asm volatile("mma.sync.aligned.m16n8k16.row.col.f32.bf16.bf16.f32 "
                 "{%0,%1,%2,%3}, {%4,%5,%6,%7}, {%8,%9}, {%0,%1,%2,%3};"
                 : "+f"(d[0]), "+f"(d[1]), "+f"(d[2]), "+f"(d[3])
                 : "r"(a0), "r"(a1), "r"(a2), "r"(a3), "r"(b0), "r"(b1));
}

// ---------------- query kernel: HMMA bf16 GEMM + fused log_softmax ----------------
// 1024 CTAs x 256 thr; tile 128 q x 64 c x K=256. warp w owns rows [16w,16w+16).
// smem: qss[128] @0, B(32KB) @512, A(64KB) @33280
#define OFF_QSS  0
#define OFF_B    512
#define OFF_A    33280
#define SMEM_QRY (OFF_A + MT * 512)

__global__ void __launch_bounds__(256, 2) k_query(const float* __restrict__ Q,
                                                  float* __restrict__ out) {
    uint32_t sb = smem_u32(smem_raw);
    float* qss = (float*)(smem_raw + OFF_QSS);
    const int tid = threadIdx.x;
    const int wid = tid >> 5;
    const int lid = tid & 31;
    const int qbase = blockIdx.x * MT;

    if (tid < MT) qss[tid] = 0.0f;

    // ---- stage B: 32KB pre-swizzled copy ----
#pragma unroll
    for (int it = 0; it < 8; it++)
        ((uint4*)(smem_raw + OFF_B))[tid + it * 256] = g_Pbf4[tid + it * 256];

    __syncthreads();   // qss zeroed before atomics below

    // ---- stage A: fp32 -> bf16 swizzled, + q sumsq ----
#pragma unroll
    for (int it = 0; it < 32; it++) {
        int f = it * 256 + tid;             // float4 index over 128 rows x 64
        int row = f >> 6;
        int col4 = f & 63;
        float4 v = __ldg(((const float4*)Q) + (size_t)(qbase + row) * (D / 4) + col4);
        __nv_bfloat162 p0 = __floats2bfloat162_rn(v.x, v.y);
        __nv_bfloat162 p1 = __floats2bfloat162_rn(v.z, v.w);
        uint2 u = { *(uint32_t*)&p0, *(uint32_t*)&p1 };
        uint32_t addr = OFF_A + row * 512 + ((((col4 >> 1) ^ (row & 7))) << 4) + ((col4 & 1) << 3);
        *(uint2*)(smem_raw + addr) = u;
        float s = v.x * v.x + v.y * v.y + v.z * v.z + v.w * v.w;
#pragma unroll
        for (int w = 16; w > 0; w >>= 1) s += __shfl_xor_sync(0xffffffffu, s, w);
        if (lid == 0) atomicAdd(&qss[row], s);
    }
    __syncthreads();

    // ---- mainloop: 16 ksteps, 8 n-tiles per warp ----
    float dA[16], dB[16];                   // rows (w*16 + lid/4) and (+8): [nt][2]
    float dacc[8][4];
#pragma unroll
    for (int nt = 0; nt < 8; nt++)
#pragma unroll
        for (int j = 0; j < 4; j++) dacc[nt][j] = 0.0f;

    // per-lane ldmatrix address components
    const int am   = lid >> 3;                       // matrix id 0..3
    const int arow = wid * 16 + (am & 1) * 8 + (lid & 7);
    const int agsel = am >> 1;                       // 0: k-lo granule, 1: k-hi
    const int brow0 = (am >> 1) * 8 + (lid & 7);     // n-tile-pair local row
    const int bgsel = am & 1;

#pragma unroll
    for (int s = 0; s < 16; s++) {
        uint32_t a0, a1, a2, a3;
        {
            uint32_t g = 2 * s + agsel;
            uint32_t addr = sb + OFF_A + arow * 512 + (((g ^ (arow & 7))) << 4);
            ldm4(a0, a1, a2, a3, addr);
        }
        uint32_t bfr[16];
#pragma unroll
        for (int pp = 0; pp < 4; pp++) {             // n-tile pairs (2 tiles each)
            int row = pp * 16 + brow0;
            uint32_t g = 2 * s + bgsel;
            uint32_t addr = sb + OFF_B + row * 512 + (((g ^ (row & 7))) << 4);
            ldm4(bfr[pp * 4 + 0], bfr[pp * 4 + 1], bfr[pp * 4 + 2], bfr[pp * 4 + 3], addr);
        }
#pragma unroll
        for (int nt = 0; nt < 8; nt++)
            mma16816(dacc[nt], a0, a1, a2, a3, bfr[nt * 2], bfr[nt * 2 + 1]);
    }
#pragma unroll
    for (int nt = 0; nt < 8; nt++) {
        dA[nt * 2] = dacc[nt][0]; dA[nt * 2 + 1] = dacc[nt][1];
        dB[nt * 2] = dacc[nt][2]; dB[nt * 2 + 1] = dacc[nt][3];
    }

    // ---- epilogue: per-row log_softmax within 4-lane quad ----
    const int rA = wid * 16 + (lid >> 2);
    const int rB = rA + 8;
    float invA = 1.0f / fmaxf(sqrtf(qss[rA]), 1e-8f);
    float invB = 1.0f / fmaxf(sqrtf(qss[rB]), 1e-8f);

    float mA = -3.4e38f, mB = -3.4e38f;
#pragma unroll
    for (int j = 0; j < 16; j++) {
        dA[j] *= invA; mA = fmaxf(mA, dA[j]);
        dB[j] *= invB; mB = fmaxf(mB, dB[j]);
    }
#pragma unroll
    for (int w = 1; w < 4; w <<= 1) {
        mA = fmaxf(mA, __shfl_xor_sync(0xffffffffu, mA, w));
        mB = fmaxf(mB, __shfl_xor_sync(0xffffffffu, mB, w));
    }
    float sA = 0.0f, sB = 0.0f;
#pragma unroll
    for (int j = 0; j < 16; j++) {
        sA += fexp(dA[j] - mA);
        sB += fexp(dB[j] - mB);
    }
#pragma unroll
    for (int w = 1; w < 4; w <<= 1) {
        sA += __shfl_xor_sync(0xffffffffu, sA, w);
        sB += __shfl_xor_sync(0xffffffffu, sB, w);
    }
    float lseA = mA + logf(sA);
    float lseB = mB + logf(sB);

    float* oA = out + (size_t)(qbase + rA) * C + (lid & 3) * 2;
    float* oB = out + (size_t)(qbase + rB) * C + (lid & 3) * 2;
#pragma unroll
    for (int nt = 0; nt < 8; nt++) {
        float2 a = { dA[nt * 2] - lseA, dA[nt * 2 + 1] - lseA };
        float2 b = { dB[nt * 2] - lseB, dB[nt * 2 + 1] - lseB };
        *(float2*)(oA + nt * 8) = a;
        *(float2*)(oB + nt * 8) = b;
    }
}

extern "C" void kernel_launch(void* const* d_in, const int* in_sizes, int n_in,
                              void* d_out, int out_size) {
    const float* support = (const float*)d_in[0];
    const int*   labels  = (const int*)d_in[1];
    const float* query   = (const float*)d_in[2];
    float*       out     = (float*)d_out;

    const int seg_smem = C * D * 4 + C * 4;     // 65792
    cudaFuncSetAttribute(k_seg,   cudaFuncAttributeMaxDynamicSharedMemorySize, seg_smem);
    cudaFuncSetAttribute(k_query, cudaFuncAttributeMaxDynamicSharedMemorySize, SMEM_QRY);

    k_zero<<<(C * D + 255) / 256, 256>>>();
    k_seg<<<NS / RPB, 256, seg_smem>>>(support, labels);
    k_fin<<<C, 64>>>();
    k_query<<<NQ / MT, 256, SMEM_QRY>>>(query, out);
}